// round 10
// baseline (speedup 1.0000x reference)
#include <cuda_runtime.h>

// ---------------- DCT-II 8-point constants (fp32, match np.float32(D)) ----
#define G_ 0.35355339059327373f
#define A_ 0.49039264020161522f
#define B_ 0.41573480615127262f
#define C_ 0.27778511650980114f
#define D_ 0.09754516100806417f
#define E_ 0.46193976625564337f
#define F_ 0.19134171618254492f

// Quant tables for QUALITY=95 in NATURAL layout, packed (q, 1/q).
#define QP(v) {(float)(v), 1.0f/(float)(v)}
__constant__ float2 c_tab2[128] = {
    // luma (natural row-major)
    QP(2),QP(1),QP(1),QP(2),QP(2),QP(4),QP(5),QP(6),
    QP(1),QP(1),QP(1),QP(2),QP(3),QP(6),QP(6),QP(6),
    QP(1),QP(1),QP(2),QP(2),QP(4),QP(6),QP(7),QP(6),
    QP(1),QP(2),QP(2),QP(3),QP(5),QP(9),QP(8),QP(6),
    QP(2),QP(2),QP(4),QP(6),QP(7),QP(11),QP(10),QP(8),
    QP(2),QP(4),QP(6),QP(6),QP(8),QP(10),QP(11),QP(9),
    QP(5),QP(6),QP(8),QP(9),QP(10),QP(12),QP(12),QP(10),
    QP(7),QP(9),QP(10),QP(10),QP(11),QP(10),QP(10),QP(10),
    // chroma (natural row-major, symmetric)
    QP(2),QP(2),QP(2),QP(5),QP(10),QP(10),QP(10),QP(10),
    QP(2),QP(2),QP(3),QP(7),QP(10),QP(10),QP(10),QP(10),
    QP(2),QP(3),QP(6),QP(10),QP(10),QP(10),QP(10),QP(10),
    QP(5),QP(7),QP(10),QP(10),QP(10),QP(10),QP(10),QP(10),
    QP(10),QP(10),QP(10),QP(10),QP(10),QP(10),QP(10),QP(10),
    QP(10),QP(10),QP(10),QP(10),QP(10),QP(10),QP(10),QP(10),
    QP(10),QP(10),QP(10),QP(10),QP(10),QP(10),QP(10),QP(10),
    QP(10),QP(10),QP(10),QP(10),QP(10),QP(10),QP(10),QP(10)
};

#define IMGW 512
#define TW   64       // tile width (pixels)
#define TH   32       // tile height (pixels)
#define SYS  68       // padded stride of Y plane in smem (64 + 4)
#define SCS  36       // padded stride of chroma planes (32 + 4)
#define NTHR 128

// round-to-nearest-even via magic constant (|x| < 2^22 guaranteed here)
__device__ __forceinline__ float rne(float v) {
    float t = fmaf(v, 1.0f, 12582912.0f);   // 1.5 * 2^23
    return fmaf(t, 1.0f, -12582912.0f);
}

__device__ __forceinline__ void fdct8(const float x[8], float o[8]) {
    float s07 = x[0] + x[7], s16 = x[1] + x[6], s25 = x[2] + x[5], s34 = x[3] + x[4];
    float d07 = x[0] - x[7], d16 = x[1] - x[6], d25 = x[2] - x[5], d34 = x[3] - x[4];
    float e0 = s07 + s34, e1 = s16 + s25, e2 = s07 - s34, e3 = s16 - s25;
    o[0] = G_ * (e0 + e1);
    o[4] = G_ * (e0 - e1);
    o[2] = fmaf( F_, e3, E_ * e2);
    o[6] = fmaf(-E_, e3, F_ * e2);
    o[1] = fmaf( D_, d34, fmaf( C_, d25, fmaf( B_, d16, A_ * d07)));
    o[3] = fmaf(-C_, d34, fmaf(-A_, d25, fmaf(-D_, d16, B_ * d07)));
    o[5] = fmaf( B_, d34, fmaf( D_, d25, fmaf(-A_, d16, C_ * d07)));
    o[7] = fmaf(-A_, d34, fmaf( B_, d25, fmaf(-C_, d16, D_ * d07)));
}

__device__ __forceinline__ void idct8(const float x[8], float o[8]) {
    float ee0 = G_ * (x[0] + x[4]);
    float ee1 = G_ * (x[0] - x[4]);
    float eo0 = fmaf( F_, x[6], E_ * x[2]);
    float eo1 = fmaf(-E_, x[6], F_ * x[2]);
    float ev0 = ee0 + eo0, ev1 = ee1 + eo1, ev2 = ee1 - eo1, ev3 = ee0 - eo0;
    float od0 = fmaf( D_, x[7], fmaf( C_, x[5], fmaf( B_, x[3], A_ * x[1])));
    float od1 = fmaf(-C_, x[7], fmaf(-A_, x[5], fmaf(-D_, x[3], B_ * x[1])));
    float od2 = fmaf( B_, x[7], fmaf( D_, x[5], fmaf(-A_, x[3], C_ * x[1])));
    float od3 = fmaf(-A_, x[7], fmaf( B_, x[5], fmaf(-C_, x[3], D_ * x[1])));
    o[0] = ev0 + od0; o[1] = ev1 + od1; o[2] = ev2 + od2; o[3] = ev3 + od3;
    o[4] = ev3 - od3; o[5] = ev2 - od2; o[6] = ev1 - od1; o[7] = ev0 - od0;
}

// Eklundh 8x8 transpose among 8 lanes (lane = k = tid&7), THREE independent
// blocks interleaved so the shfl latency chains overlap.
__device__ __forceinline__ void transpose8x3(float v0[8], float v1[8], float v2[8],
                                             int k) {
#pragma unroll
    for (int s = 1; s < 8; s <<= 1) {
        const bool up = (k & s) != 0;
#pragma unroll
        for (int j = 0; j < 8; j++) {
            if ((j & s) == 0) {
                const int jp = j | s;
                float s0 = up ? v0[j] : v0[jp];
                float s1 = up ? v1[j] : v1[jp];
                float s2 = up ? v2[j] : v2[jp];
                float r0 = __shfl_xor_sync(0xFFFFFFFFu, s0, s, 32);
                float r1 = __shfl_xor_sync(0xFFFFFFFFu, s1, s, 32);
                float r2 = __shfl_xor_sync(0xFFFFFFFFu, s2, s, 32);
                if (up) { v0[j] = r0; v1[j] = r1; v2[j] = r2; }
                else    { v0[jp] = r0; v1[jp] = r1; v2[jp] = r2; }
            }
        }
    }
}

template <int S>
__device__ __forceinline__ void storerow(float* blk, int k, const float a[8]) {
    *reinterpret_cast<float4*>(blk + k * S)     = make_float4(a[0], a[1], a[2], a[3]);
    *reinterpret_cast<float4*>(blk + k * S + 4) = make_float4(a[4], a[5], a[6], a[7]);
}
template <int S>
__device__ __forceinline__ void loadrow(const float* blk, int k, float a[8]) {
    float4 v0 = *reinterpret_cast<const float4*>(blk + k * S);
    float4 v1 = *reinterpret_cast<const float4*>(blk + k * S + 4);
    a[0] = v0.x; a[1] = v0.y; a[2] = v0.z; a[3] = v0.w;
    a[4] = v1.x; a[5] = v1.y; a[6] = v1.z; a[7] = v1.w;
}

// THREE independent 8x8 blocks (2 luma + 1 chroma) processed concurrently by
// one 8-thread group: triples ILP on the shfl/fma dependency chains.
template <int SL, int SC>
__device__ __forceinline__ void jpeg_block3(float* b0, float* b1, float* b2, int k,
                                            const float2* __restrict__ tabL,
                                            const float2* __restrict__ tabC) {
    float x0[8], x1[8], x2[8], a0[8], a1[8], a2[8];
    loadrow<SL>(b0, k, x0);
    loadrow<SL>(b1, k, x1);
    loadrow<SC>(b2, k, x2);
    fdct8(x0, a0);
    fdct8(x1, a1);
    fdct8(x2, a2);
    transpose8x3(a0, a1, a2, k);
    fdct8(a0, x0);
    fdct8(a1, x1);
    fdct8(a2, x2);
#pragma unroll
    for (int l = 0; l < 8; l++) {
        float2 t = tabL[l * 8 + k];   // shared by both luma blocks
        float2 u = tabC[l * 8 + k];
        x0[l] = rne(x0[l] * t.y) * t.x;
        x1[l] = rne(x1[l] * t.y) * t.x;
        x2[l] = rne(x2[l] * u.y) * u.x;
    }
    idct8(x0, a0);
    idct8(x1, a1);
    idct8(x2, a2);
    transpose8x3(a0, a1, a2, k);
    idct8(a0, x0);
    idct8(a1, x1);
    idct8(a2, x2);
    storerow<SL>(b0, k, x0);
    storerow<SL>(b1, k, x1);
    storerow<SC>(b2, k, x2);
}

__global__ void __launch_bounds__(NTHR, 8)
jpeg_kernel(const float* __restrict__ in, float* __restrict__ out) {
    __shared__ float sY[TH * SYS];           // 32 x 68
    __shared__ float sCb[16 * SCS];          // 16 x 36 (chroma 32x16)
    __shared__ float sCr[16 * SCS];
    __shared__ float2 sTab[128];

    const int tid = threadIdx.x;
    const int tx0 = blockIdx.x * TW;
    const int ty0 = blockIdx.y * TH;
    const int img = blockIdx.z;

    sTab[tid] = c_tab2[tid];   // 128 threads cover 128 entries; phase-1 barrier

    const float* src = in  + (((size_t)img * IMGW + ty0) * IMGW + tx0) * 3;
    float*       dst = out + (((size_t)img * IMGW + ty0) * IMGW + tx0) * 3;

    // ---------- phase 1: LDG.128, x255, RGB->YCbCr, 4:2:0 downsample ----------
    // Region = 4px wide x 2 rows. 16 col-groups x 16 row-pairs = 256 regions,
    // exactly 2 uniform iterations at 128 threads. Chroma computed from the
    // RGB sums of each 2x2 quad (color transform is linear), x0.25 folded into
    // the coefficients: cb = (-0.168736, -0.331264, 0.5)/4,
    //                   cr = (0.5, -0.418688, -0.081312)/4.
#pragma unroll
    for (int it = 0; it < 2; it++) {
        int sid = tid + it * NTHR;
        int col = sid & 15, rp = sid >> 4;
        const float* p = src + (rp * 2) * (IMGW * 3) + col * 12;
        float rs[2] = {0.0f, 0.0f}, gs[2] = {0.0f, 0.0f}, bs[2] = {0.0f, 0.0f};
#pragma unroll
        for (int dy = 0; dy < 2; dy++) {
            const float* pr = p + dy * (IMGW * 3);
            float4 q0 = *reinterpret_cast<const float4*>(pr);
            float4 q1 = *reinterpret_cast<const float4*>(pr + 4);
            float4 q2 = *reinterpret_cast<const float4*>(pr + 8);
            float rv[4] = { q0.x, q0.w, q1.z, q2.y };
            float gv[4] = { q0.y, q1.x, q1.w, q2.z };
            float bv[4] = { q0.z, q1.y, q2.x, q2.w };
            float y4[4];
#pragma unroll
            for (int i = 0; i < 4; i++) {
                // input uniform [0,1): floor(x*255) in [0,254], no clip needed
                float r = floorf(rv[i] * 255.0f);
                float g = floorf(gv[i] * 255.0f);
                float b = floorf(bv[i] * 255.0f);
                y4[i] = fmaf(r, 0.299f, fmaf(g, 0.587f, fmaf(b, 0.114f, -128.0f)));
                rs[i >> 1] += r; gs[i >> 1] += g; bs[i >> 1] += b;
            }
            *reinterpret_cast<float4*>(&sY[(rp * 2 + dy) * SYS + col * 4]) =
                make_float4(y4[0], y4[1], y4[2], y4[3]);
        }
        float cb0 = fmaf(rs[0], -0.042184f, fmaf(gs[0], -0.082816f, bs[0] * 0.125f));
        float cb1 = fmaf(rs[1], -0.042184f, fmaf(gs[1], -0.082816f, bs[1] * 0.125f));
        float cr0 = fmaf(rs[0], 0.125f, fmaf(gs[0], -0.104672f, bs[0] * (-0.020328f)));
        float cr1 = fmaf(rs[1], 0.125f, fmaf(gs[1], -0.104672f, bs[1] * (-0.020328f)));
        *reinterpret_cast<float2*>(&sCb[rp * SCS + col * 2]) = make_float2(cb0, cb1);
        *reinterpret_cast<float2*>(&sCr[rp * SCS + col * 2]) = make_float2(cr0, cr1);
    }
    __syncthreads();

    // ---------- phase 2: 16 groups x 3 blocks (2 luma + 1 chroma) interleaved --
    {
        const int grp = tid >> 3;   // 0..15
        const int k   = tid & 7;

        const float2* tl = sTab;        // luma (q, 1/q) natural layout
        const float2* tc2 = sTab + 64;  // chroma

        // luma: 8 block-cols x 4 block-rows; group handles rows (grp>>3) and +2
        float* yb0 = sY + (grp >> 3) * (8 * SYS) + (grp & 7) * 8;
        float* yb1 = sY + ((grp >> 3) + 2) * (8 * SYS) + (grp & 7) * 8;

        // chroma: 4 block-cols x 2 block-rows per plane; grp<8 -> Cb, else Cr
        int cg = grp & 7;
        float* cbase = (grp < 8) ? sCb : sCr;
        float* cb = cbase + (cg >> 2) * (8 * SCS) + (cg & 3) * 8;

        jpeg_block3<SYS, SCS>(yb0, yb1, cb, k, tl, tc2);
    }
    __syncthreads();

    // ---------- phase 3: upsample chroma, YCbCr->RGB, rne, saturate-scale -----
    // round(clip(v,0,255))/255 == clip(round(v),0,255)/255 == sat(rne(v)/255):
    // the clamp folds into FMUL.SAT for free.
#pragma unroll
    for (int it = 0; it < 2; it++) {
        int sid = tid + it * NTHR;
        int col = sid & 15, rp = sid >> 4;
        float2 cb2 = *reinterpret_cast<const float2*>(&sCb[rp * SCS + col * 2]);
        float2 cr2 = *reinterpret_cast<const float2*>(&sCr[rp * SCS + col * 2]);
        float cbv[4] = { cb2.x, cb2.x, cb2.y, cb2.y };
        float crv[4] = { cr2.x, cr2.x, cr2.y, cr2.y };
        float* p = dst + (rp * 2) * (IMGW * 3) + col * 12;
#pragma unroll
        for (int dy = 0; dy < 2; dy++) {
            float4 y4 = *reinterpret_cast<const float4*>(&sY[(rp * 2 + dy) * SYS + col * 4]);
            float yv[4] = { y4.x, y4.y, y4.z, y4.w };
            float o[12];
#pragma unroll
            for (int i = 0; i < 4; i++) {
                float y128 = yv[i] + 128.0f;
                float r2 = fmaf(crv[i], 1.402f, y128);
                float g2 = fmaf(cbv[i], -0.344136f, fmaf(crv[i], -0.714136f, y128));
                float b2 = fmaf(cbv[i], 1.772f, y128);
                o[i*3+0] = __saturatef(rne(r2) * (1.0f / 255.0f));
                o[i*3+1] = __saturatef(rne(g2) * (1.0f / 255.0f));
                o[i*3+2] = __saturatef(rne(b2) * (1.0f / 255.0f));
            }
            float* pr = p + dy * (IMGW * 3);
            *reinterpret_cast<float4*>(pr)     = make_float4(o[0], o[1], o[2], o[3]);
            *reinterpret_cast<float4*>(pr + 4) = make_float4(o[4], o[5], o[6], o[7]);
            *reinterpret_cast<float4*>(pr + 8) = make_float4(o[8], o[9], o[10], o[11]);
        }
    }
}

extern "C" void kernel_launch(void* const* d_in, const int* in_sizes, int n_in,
                              void* d_out, int out_size) {
    (void)in_sizes; (void)n_in; (void)out_size;
    dim3 grid(IMGW / TW, IMGW / TH, 32);
    jpeg_kernel<<<grid, NTHR>>>((const float*)d_in[0], (float*)d_out);
}

// round 11
// speedup vs baseline: 1.0224x; 1.0224x over previous
#include <cuda_runtime.h>

// ---------------- DCT-II 8-point constants (fp32, match np.float32(D)) ----
#define G_ 0.35355339059327373f
#define A_ 0.49039264020161522f
#define B_ 0.41573480615127262f
#define C_ 0.27778511650980114f
#define D_ 0.09754516100806417f
#define E_ 0.46193976625564337f
#define F_ 0.19134171618254492f

// Quant tables for QUALITY=95 in NATURAL layout, packed (q, 1/q).
#define QP(v) {(float)(v), 1.0f/(float)(v)}
__constant__ float2 c_tab2[128] = {
    // luma (natural row-major)
    QP(2),QP(1),QP(1),QP(2),QP(2),QP(4),QP(5),QP(6),
    QP(1),QP(1),QP(1),QP(2),QP(3),QP(6),QP(6),QP(6),
    QP(1),QP(1),QP(2),QP(2),QP(4),QP(6),QP(7),QP(6),
    QP(1),QP(2),QP(2),QP(3),QP(5),QP(9),QP(8),QP(6),
    QP(2),QP(2),QP(4),QP(6),QP(7),QP(11),QP(10),QP(8),
    QP(2),QP(4),QP(6),QP(6),QP(8),QP(10),QP(11),QP(9),
    QP(5),QP(6),QP(8),QP(9),QP(10),QP(12),QP(12),QP(10),
    QP(7),QP(9),QP(10),QP(10),QP(11),QP(10),QP(10),QP(10),
    // chroma (natural row-major, symmetric)
    QP(2),QP(2),QP(2),QP(5),QP(10),QP(10),QP(10),QP(10),
    QP(2),QP(2),QP(3),QP(7),QP(10),QP(10),QP(10),QP(10),
    QP(2),QP(3),QP(6),QP(10),QP(10),QP(10),QP(10),QP(10),
    QP(5),QP(7),QP(10),QP(10),QP(10),QP(10),QP(10),QP(10),
    QP(10),QP(10),QP(10),QP(10),QP(10),QP(10),QP(10),QP(10),
    QP(10),QP(10),QP(10),QP(10),QP(10),QP(10),QP(10),QP(10),
    QP(10),QP(10),QP(10),QP(10),QP(10),QP(10),QP(10),QP(10),
    QP(10),QP(10),QP(10),QP(10),QP(10),QP(10),QP(10),QP(10)
};

#define IMGW 512
#define TW   64       // tile width (pixels)
#define TH   32       // tile height (pixels)
#define SYS  68       // padded stride of Y plane in smem (64 + 4)
#define SCS  36       // padded stride of chroma planes (32 + 4)
#define NTHR 128

// round-to-nearest-even via magic constant (|x| < 2^22 guaranteed here)
__device__ __forceinline__ float rne(float v) {
    float t = fmaf(v, 1.0f, 12582912.0f);   // 1.5 * 2^23
    return fmaf(t, 1.0f, -12582912.0f);
}

__device__ __forceinline__ void fdct8(const float x[8], float o[8]) {
    float s07 = x[0] + x[7], s16 = x[1] + x[6], s25 = x[2] + x[5], s34 = x[3] + x[4];
    float d07 = x[0] - x[7], d16 = x[1] - x[6], d25 = x[2] - x[5], d34 = x[3] - x[4];
    float e0 = s07 + s34, e1 = s16 + s25, e2 = s07 - s34, e3 = s16 - s25;
    o[0] = G_ * (e0 + e1);
    o[4] = G_ * (e0 - e1);
    o[2] = fmaf( F_, e3, E_ * e2);
    o[6] = fmaf(-E_, e3, F_ * e2);
    o[1] = fmaf( D_, d34, fmaf( C_, d25, fmaf( B_, d16, A_ * d07)));
    o[3] = fmaf(-C_, d34, fmaf(-A_, d25, fmaf(-D_, d16, B_ * d07)));
    o[5] = fmaf( B_, d34, fmaf( D_, d25, fmaf(-A_, d16, C_ * d07)));
    o[7] = fmaf(-A_, d34, fmaf( B_, d25, fmaf(-C_, d16, D_ * d07)));
}

__device__ __forceinline__ void idct8(const float x[8], float o[8]) {
    float ee0 = G_ * (x[0] + x[4]);
    float ee1 = G_ * (x[0] - x[4]);
    float eo0 = fmaf( F_, x[6], E_ * x[2]);
    float eo1 = fmaf(-E_, x[6], F_ * x[2]);
    float ev0 = ee0 + eo0, ev1 = ee1 + eo1, ev2 = ee1 - eo1, ev3 = ee0 - eo0;
    float od0 = fmaf( D_, x[7], fmaf( C_, x[5], fmaf( B_, x[3], A_ * x[1])));
    float od1 = fmaf(-C_, x[7], fmaf(-A_, x[5], fmaf(-D_, x[3], B_ * x[1])));
    float od2 = fmaf( B_, x[7], fmaf( D_, x[5], fmaf(-A_, x[3], C_ * x[1])));
    float od3 = fmaf(-A_, x[7], fmaf( B_, x[5], fmaf(-C_, x[3], D_ * x[1])));
    o[0] = ev0 + od0; o[1] = ev1 + od1; o[2] = ev2 + od2; o[3] = ev3 + od3;
    o[4] = ev3 - od3; o[5] = ev2 - od2; o[6] = ev1 - od1; o[7] = ev0 - od0;
}

// Eklundh 8x8 transpose among 8 lanes (lane = k = tid&7), THREE independent
// blocks interleaved so the shfl latency chains overlap.
__device__ __forceinline__ void transpose8x3(float v0[8], float v1[8], float v2[8],
                                             int k) {
#pragma unroll
    for (int s = 1; s < 8; s <<= 1) {
        const bool up = (k & s) != 0;
#pragma unroll
        for (int j = 0; j < 8; j++) {
            if ((j & s) == 0) {
                const int jp = j | s;
                float s0 = up ? v0[j] : v0[jp];
                float s1 = up ? v1[j] : v1[jp];
                float s2 = up ? v2[j] : v2[jp];
                float r0 = __shfl_xor_sync(0xFFFFFFFFu, s0, s, 32);
                float r1 = __shfl_xor_sync(0xFFFFFFFFu, s1, s, 32);
                float r2 = __shfl_xor_sync(0xFFFFFFFFu, s2, s, 32);
                if (up) { v0[j] = r0; v1[j] = r1; v2[j] = r2; }
                else    { v0[jp] = r0; v1[jp] = r1; v2[jp] = r2; }
            }
        }
    }
}

template <int S>
__device__ __forceinline__ void storerow(float* blk, int k, const float a[8]) {
    *reinterpret_cast<float4*>(blk + k * S)     = make_float4(a[0], a[1], a[2], a[3]);
    *reinterpret_cast<float4*>(blk + k * S + 4) = make_float4(a[4], a[5], a[6], a[7]);
}
template <int S>
__device__ __forceinline__ void loadrow(const float* blk, int k, float a[8]) {
    float4 v0 = *reinterpret_cast<const float4*>(blk + k * S);
    float4 v1 = *reinterpret_cast<const float4*>(blk + k * S + 4);
    a[0] = v0.x; a[1] = v0.y; a[2] = v0.z; a[3] = v0.w;
    a[4] = v1.x; a[5] = v1.y; a[6] = v1.z; a[7] = v1.w;
}

// THREE independent 8x8 blocks (2 luma + 1 chroma) processed concurrently by
// one 8-thread group: triples ILP on the shfl/fma dependency chains.
template <int SL, int SC>
__device__ __forceinline__ void jpeg_block3(float* b0, float* b1, float* b2, int k,
                                            const float2* __restrict__ tabL,
                                            const float2* __restrict__ tabC) {
    float x0[8], x1[8], x2[8], a0[8], a1[8], a2[8];
    loadrow<SL>(b0, k, x0);
    loadrow<SL>(b1, k, x1);
    loadrow<SC>(b2, k, x2);
    fdct8(x0, a0);
    fdct8(x1, a1);
    fdct8(x2, a2);
    transpose8x3(a0, a1, a2, k);
    fdct8(a0, x0);
    fdct8(a1, x1);
    fdct8(a2, x2);
#pragma unroll
    for (int l = 0; l < 8; l++) {
        float2 t = tabL[l * 8 + k];   // shared by both luma blocks
        float2 u = tabC[l * 8 + k];
        x0[l] = rne(x0[l] * t.y) * t.x;
        x1[l] = rne(x1[l] * t.y) * t.x;
        x2[l] = rne(x2[l] * u.y) * u.x;
    }
    idct8(x0, a0);
    idct8(x1, a1);
    idct8(x2, a2);
    transpose8x3(a0, a1, a2, k);
    idct8(a0, x0);
    idct8(a1, x1);
    idct8(a2, x2);
    storerow<SL>(b0, k, x0);
    storerow<SL>(b1, k, x1);
    storerow<SC>(b2, k, x2);
}

__global__ void __launch_bounds__(NTHR, 7)
jpeg_kernel(const float* __restrict__ in, float* __restrict__ out) {
    __shared__ float sY[TH * SYS];           // 32 x 68
    __shared__ float sCb[16 * SCS];          // 16 x 36 (chroma 32x16)
    __shared__ float sCr[16 * SCS];
    __shared__ float2 sTab[128];

    const int tid = threadIdx.x;
    const int tx0 = blockIdx.x * TW;
    const int ty0 = blockIdx.y * TH;
    const int img = blockIdx.z;

    sTab[tid] = c_tab2[tid];   // 128 threads cover 128 entries; phase-1 barrier

    const float* src = in  + (((size_t)img * IMGW + ty0) * IMGW + tx0) * 3;
    float*       dst = out + (((size_t)img * IMGW + ty0) * IMGW + tx0) * 3;

    // ---------- phase 1: LDG.128, x255, RGB->YCbCr, 4:2:0 downsample ----------
    // Region = 4px wide x 2 rows. 16 col-groups x 16 row-pairs = 256 regions,
    // exactly 2 uniform iterations at 128 threads. Chroma computed from the
    // RGB sums of each 2x2 quad (color transform is linear), x0.25 folded into
    // the coefficients: cb = (-0.168736, -0.331264, 0.5)/4,
    //                   cr = (0.5, -0.418688, -0.081312)/4.
#pragma unroll
    for (int it = 0; it < 2; it++) {
        int sid = tid + it * NTHR;
        int col = sid & 15, rp = sid >> 4;
        const float* p = src + (rp * 2) * (IMGW * 3) + col * 12;
        float rs[2] = {0.0f, 0.0f}, gs[2] = {0.0f, 0.0f}, bs[2] = {0.0f, 0.0f};
#pragma unroll
        for (int dy = 0; dy < 2; dy++) {
            const float* pr = p + dy * (IMGW * 3);
            float4 q0 = *reinterpret_cast<const float4*>(pr);
            float4 q1 = *reinterpret_cast<const float4*>(pr + 4);
            float4 q2 = *reinterpret_cast<const float4*>(pr + 8);
            float rv[4] = { q0.x, q0.w, q1.z, q2.y };
            float gv[4] = { q0.y, q1.x, q1.w, q2.z };
            float bv[4] = { q0.z, q1.y, q2.x, q2.w };
            float y4[4];
#pragma unroll
            for (int i = 0; i < 4; i++) {
                // input uniform [0,1): floor(x*255) in [0,254], no clip needed
                float r = floorf(rv[i] * 255.0f);
                float g = floorf(gv[i] * 255.0f);
                float b = floorf(bv[i] * 255.0f);
                y4[i] = fmaf(r, 0.299f, fmaf(g, 0.587f, fmaf(b, 0.114f, -128.0f)));
                rs[i >> 1] += r; gs[i >> 1] += g; bs[i >> 1] += b;
            }
            *reinterpret_cast<float4*>(&sY[(rp * 2 + dy) * SYS + col * 4]) =
                make_float4(y4[0], y4[1], y4[2], y4[3]);
        }
        float cb0 = fmaf(rs[0], -0.042184f, fmaf(gs[0], -0.082816f, bs[0] * 0.125f));
        float cb1 = fmaf(rs[1], -0.042184f, fmaf(gs[1], -0.082816f, bs[1] * 0.125f));
        float cr0 = fmaf(rs[0], 0.125f, fmaf(gs[0], -0.104672f, bs[0] * (-0.020328f)));
        float cr1 = fmaf(rs[1], 0.125f, fmaf(gs[1], -0.104672f, bs[1] * (-0.020328f)));
        *reinterpret_cast<float2*>(&sCb[rp * SCS + col * 2]) = make_float2(cb0, cb1);
        *reinterpret_cast<float2*>(&sCr[rp * SCS + col * 2]) = make_float2(cr0, cr1);
    }
    __syncthreads();

    // ---------- phase 2: 16 groups x 3 blocks (2 luma + 1 chroma) interleaved --
    {
        const int grp = tid >> 3;   // 0..15
        const int k   = tid & 7;

        const float2* tl = sTab;        // luma (q, 1/q) natural layout
        const float2* tc2 = sTab + 64;  // chroma

        // luma: 8 block-cols x 4 block-rows; group handles rows (grp>>3) and +2
        float* yb0 = sY + (grp >> 3) * (8 * SYS) + (grp & 7) * 8;
        float* yb1 = sY + ((grp >> 3) + 2) * (8 * SYS) + (grp & 7) * 8;

        // chroma: 4 block-cols x 2 block-rows per plane; grp<8 -> Cb, else Cr
        int cg = grp & 7;
        float* cbase = (grp < 8) ? sCb : sCr;
        float* cb = cbase + (cg >> 2) * (8 * SCS) + (cg & 3) * 8;

        jpeg_block3<SYS, SCS>(yb0, yb1, cb, k, tl, tc2);
    }
    __syncthreads();

    // ---------- phase 3: upsample chroma, YCbCr->RGB, rne, saturate-scale -----
    // round(clip(v,0,255))/255 == clip(round(v),0,255)/255 == sat(rne(v)/255):
    // the clamp folds into FMUL.SAT for free.
#pragma unroll
    for (int it = 0; it < 2; it++) {
        int sid = tid + it * NTHR;
        int col = sid & 15, rp = sid >> 4;
        float2 cb2 = *reinterpret_cast<const float2*>(&sCb[rp * SCS + col * 2]);
        float2 cr2 = *reinterpret_cast<const float2*>(&sCr[rp * SCS + col * 2]);
        float cbv[4] = { cb2.x, cb2.x, cb2.y, cb2.y };
        float crv[4] = { cr2.x, cr2.x, cr2.y, cr2.y };
        float* p = dst + (rp * 2) * (IMGW * 3) + col * 12;
#pragma unroll
        for (int dy = 0; dy < 2; dy++) {
            float4 y4 = *reinterpret_cast<const float4*>(&sY[(rp * 2 + dy) * SYS + col * 4]);
            float yv[4] = { y4.x, y4.y, y4.z, y4.w };
            float o[12];
#pragma unroll
            for (int i = 0; i < 4; i++) {
                float y128 = yv[i] + 128.0f;
                float r2 = fmaf(crv[i], 1.402f, y128);
                float g2 = fmaf(cbv[i], -0.344136f, fmaf(crv[i], -0.714136f, y128));
                float b2 = fmaf(cbv[i], 1.772f, y128);
                o[i*3+0] = __saturatef(rne(r2) * (1.0f / 255.0f));
                o[i*3+1] = __saturatef(rne(g2) * (1.0f / 255.0f));
                o[i*3+2] = __saturatef(rne(b2) * (1.0f / 255.0f));
            }
            float* pr = p + dy * (IMGW * 3);
            *reinterpret_cast<float4*>(pr)     = make_float4(o[0], o[1], o[2], o[3]);
            *reinterpret_cast<float4*>(pr + 4) = make_float4(o[4], o[5], o[6], o[7]);
            *reinterpret_cast<float4*>(pr + 8) = make_float4(o[8], o[9], o[10], o[11]);
        }
    }
}

extern "C" void kernel_launch(void* const* d_in, const int* in_sizes, int n_in,
                              void* d_out, int out_size) {
    (void)in_sizes; (void)n_in; (void)out_size;
    dim3 grid(IMGW / TW, IMGW / TH, 32);
    jpeg_kernel<<<grid, NTHR>>>((const float*)d_in[0], (float*)d_out);
}